// round 15
// baseline (speedup 1.0000x reference)
#include <cuda_runtime.h>
#include <cuda_fp16.h>
#include <math.h>
#include <stdint.h>

#define B 2
#define L 2048
#define HID 512
#define NH 8
#define HD 64
#define SAMPLE_K 40
#define N_TOP 40
#define QG 8   // queries per attention block

// ===================== helpers ==============================================
__device__ __forceinline__ uint32_t smem_u32(const void* p) {
    uint32_t a;
    asm("{ .reg .u64 t; cvta.to.shared.u64 t, %1; cvt.u32.u64 %0, t; }"
        : "=r"(a) : "l"(p));
    return a;
}

// ===================== scratch ==============================================
__device__ float g_q[B * L * HID];
__device__ float g_k[B * L * HID];
__device__ float g_v[B * L * HID];
__device__ float g_m[B * NH * L];
__device__ int   g_mtop[B * NH * N_TOP];
__device__ int   g_qmap[B * NH * L];
__device__ float g_vmean[B * NH * HD];
__device__ float g_ctxsel[B * NH * N_TOP * HD];
// fp16 hi/lo weight splits
__device__ __half g_wh[4 * HID * HID];   // Wq,Wk,Wv,Wo
__device__ __half g_wl[4 * HID * HID];

// ===================== fp32 -> fp16 hi/lo split (float4) ====================
__device__ __forceinline__ void split4_store(float4 v, __half* hi,
                                             __half* lo, size_t i4) {
    __half h0 = __float2half_rn(v.x);
    __half h1 = __float2half_rn(v.y);
    __half h2 = __float2half_rn(v.z);
    __half h3 = __float2half_rn(v.w);
    __half2* hp = (__half2*)(hi + i4 * 4);
    __half2* lp = (__half2*)(lo + i4 * 4);
    hp[0] = __half2(h0, h1);
    hp[1] = __half2(h2, h3);
    lp[0] = __half2(__float2half_rn(v.x - __half2float(h0)),
                    __float2half_rn(v.y - __half2float(h1)));
    lp[1] = __half2(__float2half_rn(v.z - __half2float(h2)),
                    __float2half_rn(v.w - __half2float(h3)));
}

// ===================== weights split + qmap init (1152 blocks) ==============
__global__ void split_w(const float* __restrict__ w0,
                        const float* __restrict__ w1,
                        const float* __restrict__ w2,
                        const float* __restrict__ w3) {
    const int NW4 = HID * HID / 4;   // 65536
    int bid = blockIdx.x;
    int tid = threadIdx.x;
    if (bid < 1024) {
        int sel = bid >> 8;
        int i = (bid & 255) * 256 + tid;
        const float* w = sel == 0 ? w0 : (sel == 1 ? w1 : (sel == 2 ? w2 : w3));
        split4_store(((const float4*)w)[i], g_wh, g_wl,
                     (size_t)sel * NW4 + i);
    } else {
        int i = (bid - 1024) * 256 + tid;
        if (i < B * NH * L) g_qmap[i] = -1;
    }
}

// ===================== HMMA split-fp16 GEMM tile (TM=64) ====================
#define TM 64
#define TN 128
#define KC 32
#define NCH (HID / KC)                 // 16
#define TILE_A (TM * KC * 2)           // 4096
#define TILE_BB (TN * KC * 2)          // 8192
#define STAGE_B (2 * TILE_A + 2 * TILE_BB)  // 24576
#define NSTG 3
#define GEMM_SMEM (NSTG * STAGE_B)     // 73728

__device__ __forceinline__ uint32_t swz(uint32_t off) {
    return off ^ ((off >> 3) & 0x30);
}

__device__ __forceinline__ void ldsm4(uint32_t r[4], uint32_t tile,
                                      int rowbase, int ks) {
    int lane = threadIdx.x & 31;
    int row = rowbase + (lane & 15);
    int c16 = ks * 2 + (lane >> 4);
    uint32_t addr = tile + swz((uint32_t)(row * 64 + c16 * 16));
    asm volatile("ldmatrix.sync.aligned.m8n8.x4.shared.b16 {%0,%1,%2,%3}, [%4];"
                 : "=r"(r[0]), "=r"(r[1]), "=r"(r[2]), "=r"(r[3]) : "r"(addr));
}

__device__ __forceinline__ void mma16816(float c[4], const uint32_t a[4],
                                         uint32_t b0, uint32_t b1) {
    asm volatile(
        "mma.sync.aligned.m16n8k16.row.col.f32.f16.f16.f32 "
        "{%0,%1,%2,%3},{%4,%5,%6,%7},{%8,%9},{%0,%1,%2,%3};"
        : "+f"(c[0]), "+f"(c[1]), "+f"(c[2]), "+f"(c[3])
        : "r"(a[0]), "r"(a[1]), "r"(a[2]), "r"(a[3]), "r"(b0), "r"(b1));
}

// convert 8 fp32 -> hi/lo fp16 and store swizzled
__device__ __forceinline__ void store_a_hilo(char* smem_stage,
                                             const float* __restrict__ src,
                                             int row, int seg) {
    float4 v0 = ((const float4*)src)[0];
    float4 v1 = ((const float4*)src)[1];
    float f[8] = {v0.x, v0.y, v0.z, v0.w, v1.x, v1.y, v1.z, v1.w};
    __half hi[8], lo[8];
#pragma unroll
    for (int i = 0; i < 8; i++) {
        hi[i] = __float2half_rn(f[i]);
        lo[i] = __float2half_rn(f[i] - __half2float(hi[i]));
    }
    uint32_t off = swz((uint32_t)(row * 64 + seg * 16));
    *(uint4*)(smem_stage + off) = *(const uint4*)hi;
    *(uint4*)(smem_stage + TILE_A + off) = *(const uint4*)lo;
}

// gemm tile: A gathered fp32 (inline hi/lo convert), B from weight splits.
template <bool TWO>
__device__ __forceinline__ void gemm_tile(
    const float* __restrict__ Araw,
    const __half* __restrict__ Bh, const __half* __restrict__ Bl,
    const float* __restrict__ bias, float* __restrict__ out,
    int m0, int n0g, int n0l, char* smem) {
    const uint32_t sbase = smem_u32(smem);

    const int tid = threadIdx.x;
    const int wid = tid >> 5;
    const int wm = wid >> 2;
    const int wn = wid & 3;
    const int lane = tid & 31;

    float acc[2][4][4];
#pragma unroll
    for (int i = 0; i < 2; i++)
#pragma unroll
        for (int j = 0; j < 4; j++)
#pragma unroll
            for (int t = 0; t < 4; t++) acc[i][j][t] = 0.0f;

    auto load_chunk = [&](int c, int stg) {
        const int k0 = c * KC;
        const uint32_t sb = sbase + stg * STAGE_B;
        // B tiles first (async, in flight during the A gather)
#pragma unroll
        for (int t = 0; t < (TWO ? 1 : 2); t++) {
            const __half* src0 = t ? Bl : Bh;
            const uint32_t tile = sb + 2 * TILE_A + t * TILE_BB;
#pragma unroll
            for (int i = 0; i < 2; i++) {
                int idx = tid + i * 256;
                int row = idx >> 2;
                int c16 = idx & 3;
                const void* src =
                    src0 + (size_t)(n0g + row) * HID + k0 + c16 * 8;
                uint32_t dst = tile + swz((uint32_t)(row * 64 + c16 * 16));
                asm volatile("cp.async.cg.shared.global [%0], [%1], 16;"
                             :: "r"(dst), "l"(src));
            }
        }
        // A tile: fp32 gather + inline hi/lo conversion
        {
            int row = tid >> 2;
            int seg = tid & 3;
            const float* src =
                Araw + (size_t)(m0 + row) * HID + k0 + seg * 8;
            store_a_hilo(smem + stg * STAGE_B, src, row, seg);
        }
    };

    load_chunk(0, 0);
    asm volatile("cp.async.commit_group;" ::: "memory");
    load_chunk(1, 1);
    asm volatile("cp.async.commit_group;" ::: "memory");

    for (int c = 0; c < NCH; c++) {
        if (c + 1 < NCH)
            asm volatile("cp.async.wait_group 1;" ::: "memory");
        else
            asm volatile("cp.async.wait_group 0;" ::: "memory");
        __syncthreads();
        if (c + 2 < NCH) {
            load_chunk(c + 2, (c + 2) % NSTG);
            asm volatile("cp.async.commit_group;" ::: "memory");
        }

        const uint32_t stg = sbase + (c % NSTG) * STAGE_B;
        const uint32_t tAh = stg;
        const uint32_t tAl = stg + TILE_A;
        const uint32_t tBh = stg + 2 * TILE_A;
        const uint32_t tBl = tBh + TILE_BB;

#pragma unroll
        for (int ks = 0; ks < 2; ks++) {
            uint32_t a[2][4], bb[2][4];
            // term 1: Ah * Bh
#pragma unroll
            for (int mf = 0; mf < 2; mf++)
                ldsm4(a[mf], tAh, wm * 32 + mf * 16, ks);
#pragma unroll
            for (int p = 0; p < 2; p++)
                ldsm4(bb[p], tBh, wn * 32 + p * 16, ks);
#pragma unroll
            for (int mf = 0; mf < 2; mf++)
#pragma unroll
                for (int nf = 0; nf < 4; nf++) {
                    int p = nf >> 1, q = nf & 1;
                    mma16816(acc[mf][nf], a[mf], bb[p][q], bb[p][q + 2]);
                }
            // term 2: Al * Bh (reuse B frags)
#pragma unroll
            for (int mf = 0; mf < 2; mf++)
                ldsm4(a[mf], tAl, wm * 32 + mf * 16, ks);
#pragma unroll
            for (int mf = 0; mf < 2; mf++)
#pragma unroll
                for (int nf = 0; nf < 4; nf++) {
                    int p = nf >> 1, q = nf & 1;
                    mma16816(acc[mf][nf], a[mf], bb[p][q], bb[p][q + 2]);
                }
            // term 3 (3-term only): Ah * Bl
            if (!TWO) {
#pragma unroll
                for (int mf = 0; mf < 2; mf++)
                    ldsm4(a[mf], tAh, wm * 32 + mf * 16, ks);
#pragma unroll
                for (int p = 0; p < 2; p++)
                    ldsm4(bb[p], tBl, wn * 32 + p * 16, ks);
#pragma unroll
                for (int mf = 0; mf < 2; mf++)
#pragma unroll
                    for (int nf = 0; nf < 4; nf++) {
                        int p = nf >> 1, q = nf & 1;
                        mma16816(acc[mf][nf], a[mf], bb[p][q], bb[p][q + 2]);
                    }
            }
        }
    }

    const int r0 = m0 + wm * 32;
    const int c0 = n0l + wn * 32;
#pragma unroll
    for (int mf = 0; mf < 2; mf++) {
#pragma unroll
        for (int nf = 0; nf < 4; nf++) {
            int row = r0 + mf * 16 + (lane >> 2);
            int col = c0 + nf * 8 + (lane & 3) * 2;
            float bu0 = bias[col], bu1 = bias[col + 1];
            out[(size_t)row * HID + col]           = acc[mf][nf][0] + bu0;
            out[(size_t)row * HID + col + 1]       = acc[mf][nf][1] + bu1;
            out[(size_t)(row + 8) * HID + col]     = acc[mf][nf][2] + bu0;
            out[(size_t)(row + 8) * HID + col + 1] = acc[mf][nf][3] + bu1;
        }
    }
}

// ===================== QK GEMM (3-term, 512 CTAs) ===========================
__global__ void __launch_bounds__(256, 3)
qk_kernel(const float* __restrict__ hidden,
          const __half* __restrict__ Bh, const __half* __restrict__ Bl,
          const float* __restrict__ bq, const float* __restrict__ bk,
          float* __restrict__ oq, float* __restrict__ ok) {
    extern __shared__ char smem[];
    int sel = blockIdx.x >> 2;
    gemm_tile<false>(hidden, Bh, Bl, sel ? bk : bq, sel ? ok : oq,
                     blockIdx.y * TM, blockIdx.x * TN, (blockIdx.x & 3) * TN,
                     smem);
}

// ===================== top-k body (uses caller smem) ========================
__device__ void topk_body(int bh, char* smembuf) {
    float* sval = (float*)smembuf;            // L floats
    float* wv = sval + L;                     // 8 floats
    int* wi = (int*)(wv + 8);                 // 8 ints
    int tid = threadIdx.x, lane = tid & 31, w = tid >> 5;

    for (int i = tid; i < L; i += 256) sval[i] = g_m[(size_t)bh * L + i];
    __syncthreads();

    for (int t = 0; t < N_TOP; t++) {
        float best = -INFINITY;
        int bi = 0x7fffffff;
        for (int i = tid; i < L; i += 256) {
            float v = sval[i];
            if (v > best) { best = v; bi = i; }
        }
#pragma unroll
        for (int o = 16; o; o >>= 1) {
            float ov = __shfl_xor_sync(0xffffffffu, best, o);
            int oi = __shfl_xor_sync(0xffffffffu, bi, o);
            if (ov > best || (ov == best && oi < bi)) { best = ov; bi = oi; }
        }
        if (lane == 0) { wv[w] = best; wi[w] = bi; }
        __syncthreads();
        if (tid < 8) {
            best = wv[tid];
            bi = wi[tid];
#pragma unroll
            for (int o = 4; o; o >>= 1) {
                float ov = __shfl_xor_sync(0xffu, best, o, 8);
                int oi = __shfl_xor_sync(0xffu, bi, o, 8);
                if (ov > best || (ov == best && oi < bi)) { best = ov; bi = oi; }
            }
            if (tid == 0) {
                g_mtop[bh * N_TOP + t] = bi;
                g_qmap[(size_t)bh * L + bi] = t;
                sval[bi] = -INFINITY;
            }
        }
        __syncthreads();
    }
}

// ===================== fused: V projection (256) + top-k (16) ===============
__global__ void __launch_bounds__(256, 3)
v_topk_kernel(const float* __restrict__ hidden,
              const __half* __restrict__ Bh, const __half* __restrict__ Bl,
              const float* __restrict__ bias, float* __restrict__ out) {
    extern __shared__ char smem[];
    int bid = blockIdx.x;
    if (bid < 256) {
        int nb = bid & 3, mb = bid >> 2;
        gemm_tile<true>(hidden, Bh, Bl, bias, out,
                        mb * TM, nb * TN, nb * TN, smem);
    } else {
        topk_body(bid - 256, smem);
    }
}

// ===================== m-score (float4, 2 samples/warp) =====================
__global__ void mscore_kernel(const int* __restrict__ idx_sample) {
    int warp = (blockIdx.x * blockDim.x + threadIdx.x) >> 5;
    int lane = threadIdx.x & 31;
    if (warp >= B * NH * L) return;
    int l = warp % L;
    int h = (warp / L) % NH;
    int b = warp / (L * NH);

    int sub = lane & 15;
    int half = lane >> 4;

    const float4* qrow =
        (const float4*)(g_q + ((size_t)b * L + l) * HID + h * HD);
    float4 q4 = qrow[sub];

    float mx = -INFINITY, sm = 0.0f;
#pragma unroll 4
    for (int it = 0; it < SAMPLE_K / 2; it++) {
        int s = 2 * it + half;
        int ls = idx_sample[l * SAMPLE_K + s];
        const float4* kr =
            (const float4*)(g_k + ((size_t)b * L + ls) * HID + h * HD);
        float4 k4 = kr[sub];
        float d = q4.x * k4.x + q4.y * k4.y + q4.z * k4.z + q4.w * k4.w;
#pragma unroll
        for (int o = 8; o; o >>= 1) d += __shfl_xor_sync(0xffffffffu, d, o);
        mx = fmaxf(mx, d);
        sm += d;
    }
    float mx2 = __shfl_down_sync(0xffffffffu, mx, 16);
    float sm2 = __shfl_down_sync(0xffffffffu, sm, 16);
    if (lane == 0)
        g_m[warp] = fmaxf(mx, mx2) - (sm + sm2) * (1.0f / (float)L);
}

// ===================== attention body (8 queries / block, MLP-tuned) ========
__device__ void attn_body(int blk, float* sc) {
    __shared__ float sq[QG][HD];
    __shared__ float inv[QG];
    __shared__ float red[4][QG][HD];

    const int tid = threadIdx.x;
    const int lane = tid & 31;
    const int w = tid >> 5;

    const int grp = blk % (N_TOP / QG);
    const int bh = blk / (N_TOP / QG);
    const int h = bh % NH;
    const int b = bh / NH;
    const int q0 = grp * QG;

#pragma unroll
    for (int r = 0; r < 2; r++) {
        int idx = tid + r * 256;
        int j = idx >> 6, d = idx & 63;
        int lq = g_mtop[bh * N_TOP + q0 + j];
        sq[j][d] = g_q[((size_t)b * L + lq) * HID + h * HD + d];
    }
    __syncthreads();

    // ---- scores with register double-buffered K row ----
    {
        const int sub = lane & 15;
        const int half = lane >> 4;
        float4 q4[QG];
#pragma unroll
        for (int j = 0; j < QG; j++) q4[j] = *(const float4*)&sq[j][sub * 4];

        const float4* kbase =
            (const float4*)(g_k + (size_t)b * L * HID + h * HD);
        const int kstride = HID / 4;  // float4 units per row

        int key = w * 2 + half;
        float4 k4 = kbase[(size_t)key * kstride + sub];
        for (int base = w * 2; base < L; base += 16) {
            int nkey = base + 16 + half;
            float4 kn;
            if (nkey < L) kn = kbase[(size_t)nkey * kstride + sub];
            int ckey = base + half;
            float dj[QG];
#pragma unroll
            for (int j = 0; j < QG; j++) {
                float d = q4[j].x * k4.x + q4[j].y * k4.y +
                          q4[j].z * k4.z + q4[j].w * k4.w;
#pragma unroll
                for (int o = 8; o; o >>= 1)
                    d += __shfl_xor_sync(0xffffffffu, d, o);
                dj[j] = d * 0.125f;
            }
            if (sub == 0) {
#pragma unroll
                for (int j = 0; j < QG; j++) sc[j * L + ckey] = dj[j];
            }
            k4 = kn;
        }
    }
    __syncthreads();

    // ---- softmax: warp w handles query row w ----
    {
        float mx = -INFINITY;
        for (int i = lane; i < L; i += 32) mx = fmaxf(mx, sc[w * L + i]);
#pragma unroll
        for (int o = 16; o; o >>= 1)
            mx = fmaxf(mx, __shfl_xor_sync(0xffffffffu, mx, o));
        float s = 0.0f;
        for (int i = lane; i < L; i += 32) {
            float e = __expf(sc[w * L + i] - mx);
            sc[w * L + i] = e;
            s += e;
        }
#pragma unroll
        for (int o = 16; o; o >>= 1) s += __shfl_xor_sync(0xffffffffu, s, o);
        if (lane == 0) inv[w] = 1.0f / s;
    }
    __syncthreads();

    // ---- ctx: 4 independent V loads per iteration (MLP=4) ----
    {
        const int g = tid >> 6;
        const int d = tid & 63;
        const float* vbase = g_v + (size_t)b * L * HID + h * HD + d;
        float acc[QG];
#pragma unroll
        for (int j = 0; j < QG; j++) acc[j] = 0.0f;
        for (int key = g; key < L; key += 16) {
            float v0 = vbase[(size_t)(key) * HID];
            float v1 = vbase[(size_t)(key + 4) * HID];
            float v2 = vbase[(size_t)(key + 8) * HID];
            float v3 = vbase[(size_t)(key + 12) * HID];
#pragma unroll
            for (int j = 0; j < QG; j++) {
                acc[j] += sc[j * L + key] * v0;
                acc[j] += sc[j * L + key + 4] * v1;
                acc[j] += sc[j * L + key + 8] * v2;
                acc[j] += sc[j * L + key + 12] * v3;
            }
        }
#pragma unroll
        for (int j = 0; j < QG; j++) red[g][j][d] = acc[j];
        __syncthreads();
        if (g == 0) {
#pragma unroll
            for (int j = 0; j < QG; j++) {
                float tot = red[0][j][d] + red[1][j][d] + red[2][j][d] +
                            red[3][j][d];
                g_ctxsel[((size_t)bh * N_TOP + q0 + j) * HD + d] =
                    tot * inv[j];
            }
        }
    }
}

__device__ void vmean_body(int bh) {
    __shared__ float sh[256];
    int b = bh / NH, h = bh % NH;
    int d = threadIdx.x % HD;
    int g = threadIdx.x / HD;
    const float* vbase = g_v + (size_t)b * L * HID + h * HD + d;
    float s = 0.0f;
    for (int l = g; l < L; l += 16) {
        s += vbase[(size_t)l * HID];
        s += vbase[(size_t)(l + 4) * HID];
        s += vbase[(size_t)(l + 8) * HID];
        s += vbase[(size_t)(l + 12) * HID];
    }
    sh[threadIdx.x] = s;
    __syncthreads();
    if (g == 0)
        g_vmean[bh * HD + d] =
            (sh[d] + sh[d + 64] + sh[d + 128] + sh[d + 192]) * (1.0f / (float)L);
}

// ===================== fused: attn (80) + vmean (16) ========================
__global__ void __launch_bounds__(256)
attn_vmean_kernel() {
    extern __shared__ float sc[];
    if (blockIdx.x < B * NH * (N_TOP / QG))
        attn_body(blockIdx.x, sc);
    else
        vmean_body(blockIdx.x - B * NH * (N_TOP / QG));
}

// ===================== out-proj GEMM with inline ctx gather =================
__global__ void __launch_bounds__(256, 3)
outproj_kernel(const __half* __restrict__ Bh,
               const float* __restrict__ bias, float* __restrict__ out) {
    extern __shared__ char smem[];
    const uint32_t sbase = smem_u32(smem);

    const int tid = threadIdx.x;
    const int wid = tid >> 5;
    const int wm = wid >> 2;
    const int wn = wid & 3;
    const int lane = tid & 31;

    const int m0 = blockIdx.y * TM;
    const int n0 = blockIdx.x * TN;

    float acc[2][4][4];
#pragma unroll
    for (int i = 0; i < 2; i++)
#pragma unroll
        for (int j = 0; j < 4; j++)
#pragma unroll
            for (int t = 0; t < 4; t++) acc[i][j][t] = 0.0f;

    auto load_chunk = [&](int c, int stg) {
        const int k0 = c * KC;
        const uint32_t sb = sbase + stg * STAGE_B;
        // B first (async)
        {
            const uint32_t tile = sb + 2 * TILE_A;
#pragma unroll
            for (int i = 0; i < 2; i++) {
                int idx = tid + i * 256;
                int row = idx >> 2;
                int c16 = idx & 3;
                const void* src =
                    Bh + (size_t)(n0 + row) * HID + k0 + c16 * 8;
                uint32_t dst = tile + swz((uint32_t)(row * 64 + c16 * 16));
                asm volatile("cp.async.cg.shared.global [%0], [%1], 16;"
                             :: "r"(dst), "l"(src));
            }
        }
        // A: gather ctx row segment, convert to hi/lo, store swizzled
        {
            int row = tid >> 2;
            int seg = tid & 3;
            int gi = m0 + row;
            int b = gi >> 11;
            int l = gi & (L - 1);
            int h = k0 >> 6;
            int hd0 = (k0 & 63) + seg * 8;
            int bh = b * NH + h;
            int qi = g_qmap[(size_t)bh * L + l];
            const float* src = (qi >= 0)
                ? &g_ctxsel[((size_t)bh * N_TOP + qi) * HD + hd0]
                : &g_vmean[bh * HD + hd0];
            store_a_hilo(smem + stg * STAGE_B, src, row, seg);
        }
    };

    load_chunk(0, 0);
    asm volatile("cp.async.commit_group;" ::: "memory");
    load_chunk(1, 1);
    asm volatile("cp.async.commit_group;" ::: "memory");

    for (int c = 0; c < NCH; c++) {
        if (c + 1 < NCH)
            asm volatile("cp.async.wait_group 1;" ::: "memory");
        else
            asm volatile("cp.async.wait_group 0;" ::: "memory");
        __syncthreads();
        if (c + 2 < NCH) {
            load_chunk(c + 2, (c + 2) % NSTG);
            asm volatile("cp.async.commit_group;" ::: "memory");
        }

        const uint32_t stg = sbase + (c % NSTG) * STAGE_B;
        const uint32_t tAh = stg;
        const uint32_t tAl = stg + TILE_A;
        const uint32_t tBh = stg + 2 * TILE_A;

#pragma unroll
        for (int ks = 0; ks < 2; ks++) {
            uint32_t a[2][4], bb[2][4];
#pragma unroll
            for (int mf = 0; mf < 2; mf++)
                ldsm4(a[mf], tAh, wm * 32 + mf * 16, ks);
#pragma unroll
            for (int p = 0; p < 2; p++)
                ldsm4(bb[p], tBh, wn * 32 + p * 16, ks);
#pragma unroll
            for (int mf = 0; mf < 2; mf++)
#pragma unroll
                for (int nf = 0; nf < 4; nf++) {
                    int p = nf >> 1, q = nf & 1;
                    mma16816(acc[mf][nf], a[mf], bb[p][q], bb[p][q + 2]);
                }
#pragma unroll
            for (int mf = 0; mf < 2; mf++)
                ldsm4(a[mf], tAl, wm * 32 + mf * 16, ks);
#pragma unroll
            for (int mf = 0; mf < 2; mf++)
#pragma unroll
                for (int nf = 0; nf < 4; nf++) {
                    int p = nf >> 1, q = nf & 1;
                    mma16816(acc[mf][nf], a[mf], bb[p][q], bb[p][q + 2]);
                }
        }
    }

    const int r0 = m0 + wm * 32;
    const int c0 = n0 + wn * 32;
#pragma unroll
    for (int mf = 0; mf < 2; mf++) {
#pragma unroll
        for (int nf = 0; nf < 4; nf++) {
            int row = r0 + mf * 16 + (lane >> 2);
            int col = c0 + nf * 8 + (lane & 3) * 2;
            float bu0 = bias[col], bu1 = bias[col + 1];
            out[(size_t)row * HID + col]           = acc[mf][nf][0] + bu0;
            out[(size_t)row * HID + col + 1]       = acc[mf][nf][1] + bu1;
            out[(size_t)(row + 8) * HID + col]     = acc[mf][nf][2] + bu0;
            out[(size_t)(row + 8) * HID + col + 1] = acc[mf][nf][3] + bu1;
        }
    }
}

// ===================== launch ===============================================
extern "C" void kernel_launch(void* const* d_in, const int* in_sizes, int n_in,
                              void* d_out, int out_size) {
    const float* hidden = (const float*)d_in[0];
    const int* idxs = (const int*)d_in[1];
    const float* Wq = (const float*)d_in[2];
    const float* bq = (const float*)d_in[3];
    const float* Wk = (const float*)d_in[4];
    const float* bk = (const float*)d_in[5];
    const float* Wv = (const float*)d_in[6];
    const float* bv = (const float*)d_in[7];
    const float* Wo = (const float*)d_in[8];
    const float* bo = (const float*)d_in[9];
    float* out = (float*)d_out;

    float *pq, *pk, *pv;
    cudaGetSymbolAddress((void**)&pq, g_q);
    cudaGetSymbolAddress((void**)&pk, g_k);
    cudaGetSymbolAddress((void**)&pv, g_v);
    __half *pwh, *pwl;
    cudaGetSymbolAddress((void**)&pwh, g_wh);
    cudaGetSymbolAddress((void**)&pwl, g_wl);

    cudaFuncSetAttribute(qk_kernel,
                         cudaFuncAttributeMaxDynamicSharedMemorySize, GEMM_SMEM);
    cudaFuncSetAttribute(v_topk_kernel,
                         cudaFuncAttributeMaxDynamicSharedMemorySize, GEMM_SMEM);
    cudaFuncSetAttribute(outproj_kernel,
                         cudaFuncAttributeMaxDynamicSharedMemorySize, GEMM_SMEM);
    cudaFuncSetAttribute(attn_vmean_kernel,
                         cudaFuncAttributeMaxDynamicSharedMemorySize,
                         QG * L * (int)sizeof(float));

    const int NW = HID * HID;

    // 1: weight splits + qmap init
    split_w<<<1152, 256>>>(Wq, Wk, Wv, Wo);
    // 2: Q,K projection (3-term, inline A convert), 512 CTAs
    dim3 qk_grid(8, (B * L) / TM);
    qk_kernel<<<qk_grid, 256, GEMM_SMEM>>>(hidden, pwh, pwl, bq, bk, pq, pk);
    // 3: m-score
    mscore_kernel<<<(B * NH * L) / 8, 256>>>(idxs);
    // 4 (profiled): V projection (256, inline A) + top-k (16)
    v_topk_kernel<<<272, 256, GEMM_SMEM>>>(
        hidden, pwh + 2 * (size_t)NW, pwl + 2 * (size_t)NW, bv, pv);
    // 5: attention (80) + v-mean (16)
    attn_vmean_kernel<<<96, 256, QG * L * sizeof(float)>>>();
    // 6: output projection with inline ctx gather (2-term)
    dim3 o_grid(4, (B * L) / TM);
    outproj_kernel<<<o_grid, 256, GEMM_SMEM>>>(pwh + 3 * (size_t)NW, bo, out);
}

// round 16
// speedup vs baseline: 1.1010x; 1.1010x over previous
#include <cuda_runtime.h>
#include <cuda_fp16.h>
#include <math.h>
#include <stdint.h>

#define B 2
#define L 2048
#define HID 512
#define NH 8
#define HD 64
#define SAMPLE_K 40
#define N_TOP 40
#define QG 8   // queries per attention block

// ===================== helpers ==============================================
__device__ __forceinline__ uint32_t smem_u32(const void* p) {
    uint32_t a;
    asm("{ .reg .u64 t; cvta.to.shared.u64 t, %1; cvt.u32.u64 %0, t; }"
        : "=r"(a) : "l"(p));
    return a;
}

// ===================== scratch ==============================================
__device__ float g_q[B * L * HID];
__device__ float g_k[B * L * HID];
__device__ float g_v[B * L * HID];
__device__ float g_m[B * NH * L];
__device__ int   g_mtop[B * NH * N_TOP];
__device__ int   g_qmap[B * NH * L];
__device__ float g_vmean[B * NH * HD];
__device__ float g_ctxsel[B * NH * N_TOP * HD];
// fp16 hi/lo splits
__device__ __half g_ah[B * L * HID];
__device__ __half g_al[B * L * HID];
__device__ __half g_wh[4 * HID * HID];   // Wq,Wk,Wv,Wo
__device__ __half g_wl[4 * HID * HID];

// ===================== fp32 -> fp16 hi/lo split (float4) ====================
__device__ __forceinline__ void split4_store(float4 v, __half* hi,
                                             __half* lo, size_t i4) {
    __half h0 = __float2half_rn(v.x);
    __half h1 = __float2half_rn(v.y);
    __half h2 = __float2half_rn(v.z);
    __half h3 = __float2half_rn(v.w);
    __half2* hp = (__half2*)(hi + i4 * 4);
    __half2* lp = (__half2*)(lo + i4 * 4);
    hp[0] = __half2(h0, h1);
    hp[1] = __half2(h2, h3);
    lp[0] = __half2(__float2half_rn(v.x - __half2float(h0)),
                    __float2half_rn(v.y - __half2float(h1)));
    lp[1] = __half2(__float2half_rn(v.z - __half2float(h2)),
                    __float2half_rn(v.w - __half2float(h3)));
}

// ===================== fused init: splits + weights + qmap ==================
__global__ void split_all(const float* __restrict__ hidden,
                          const float* __restrict__ w0,
                          const float* __restrict__ w1,
                          const float* __restrict__ w2,
                          const float* __restrict__ w3) {
    const int NW4 = HID * HID / 4;   // 65536
    int bid = blockIdx.x;
    int tid = threadIdx.x;
    if (bid < 2048) {
        int i4 = bid * 256 + tid;
        split4_store(((const float4*)hidden)[i4], g_ah, g_al, i4);
    } else if (bid < 3072) {
        int wb = bid - 2048;
        int sel = wb >> 8;
        int i = (wb & 255) * 256 + tid;
        const float* w = sel == 0 ? w0 : (sel == 1 ? w1 : (sel == 2 ? w2 : w3));
        split4_store(((const float4*)w)[i], g_wh, g_wl,
                     (size_t)sel * NW4 + i);
    } else {
        int i = (bid - 3072) * 256 + tid;
        if (i < B * NH * L) g_qmap[i] = -1;
    }
}

// ===================== HMMA split-fp16 GEMM tile (TM=64) ====================
#define TM 64
#define TN 128
#define KC 32
#define NCH (HID / KC)                 // 16
#define TILE_A (TM * KC * 2)           // 4096
#define TILE_BB (TN * KC * 2)          // 8192
#define STAGE_B (2 * TILE_A + 2 * TILE_BB)  // 24576
#define NSTG 3
#define GEMM_SMEM (NSTG * STAGE_B)     // 73728

__device__ __forceinline__ uint32_t swz(uint32_t off) {
    return off ^ ((off >> 3) & 0x30);
}

__device__ __forceinline__ void ldsm4(uint32_t r[4], uint32_t tile,
                                      int rowbase, int ks) {
    int lane = threadIdx.x & 31;
    int row = rowbase + (lane & 15);
    int c16 = ks * 2 + (lane >> 4);
    uint32_t addr = tile + swz((uint32_t)(row * 64 + c16 * 16));
    asm volatile("ldmatrix.sync.aligned.m8n8.x4.shared.b16 {%0,%1,%2,%3}, [%4];"
                 : "=r"(r[0]), "=r"(r[1]), "=r"(r[2]), "=r"(r[3]) : "r"(addr));
}

__device__ __forceinline__ void mma16816(float c[4], const uint32_t a[4],
                                         uint32_t b0, uint32_t b1) {
    asm volatile(
        "mma.sync.aligned.m16n8k16.row.col.f32.f16.f16.f32 "
        "{%0,%1,%2,%3},{%4,%5,%6,%7},{%8,%9},{%0,%1,%2,%3};"
        : "+f"(c[0]), "+f"(c[1]), "+f"(c[2]), "+f"(c[3])
        : "r"(a[0]), "r"(a[1]), "r"(a[2]), "r"(a[3]), "r"(b0), "r"(b1));
}

// generic gemm tile: A from splits, B from weight splits.
template <bool TWO>
__device__ __forceinline__ void gemm_tile(
    const __half* __restrict__ Ah, const __half* __restrict__ Al,
    const __half* __restrict__ Bh, const __half* __restrict__ Bl,
    const float* __restrict__ bias, float* __restrict__ out,
    int m0, int n0g, int n0l, char* smem) {
    const uint32_t sbase = smem_u32(smem);

    const int tid = threadIdx.x;
    const int wid = tid >> 5;
    const int wm = wid >> 2;
    const int wn = wid & 3;
    const int lane = tid & 31;

    float acc[2][4][4];
#pragma unroll
    for (int i = 0; i < 2; i++)
#pragma unroll
        for (int j = 0; j < 4; j++)
#pragma unroll
            for (int t = 0; t < 4; t++) acc[i][j][t] = 0.0f;

    auto load_chunk = [&](int c, int stg) {
        const int k0 = c * KC;
        const uint32_t sb = sbase + stg * STAGE_B;
#pragma unroll
        for (int t = 0; t < 2; t++) {
            const __half* src0 = t ? Al : Ah;
            const uint32_t tile = sb + t * TILE_A;
            int row = tid >> 2;
            int c16 = tid & 3;
            const void* src = src0 + (size_t)(m0 + row) * HID + k0 + c16 * 8;
            uint32_t dst = tile + swz((uint32_t)(row * 64 + c16 * 16));
            asm volatile("cp.async.cg.shared.global [%0], [%1], 16;"
                         :: "r"(dst), "l"(src));
        }
#pragma unroll
        for (int t = 0; t < (TWO ? 1 : 2); t++) {
            const __half* src0 = t ? Bl : Bh;
            const uint32_t tile = sb + 2 * TILE_A + t * TILE_BB;
#pragma unroll
            for (int i = 0; i < 2; i++) {
                int idx = tid + i * 256;
                int row = idx >> 2;
                int c16 = idx & 3;
                const void* src =
                    src0 + (size_t)(n0g + row) * HID + k0 + c16 * 8;
                uint32_t dst = tile + swz((uint32_t)(row * 64 + c16 * 16));
                asm volatile("cp.async.cg.shared.global [%0], [%1], 16;"
                             :: "r"(dst), "l"(src));
            }
        }
    };

    load_chunk(0, 0);
    asm volatile("cp.async.commit_group;" ::: "memory");
    load_chunk(1, 1);
    asm volatile("cp.async.commit_group;" ::: "memory");

    for (int c = 0; c < NCH; c++) {
        if (c + 1 < NCH)
            asm volatile("cp.async.wait_group 1;" ::: "memory");
        else
            asm volatile("cp.async.wait_group 0;" ::: "memory");
        __syncthreads();
        if (c + 2 < NCH) {
            load_chunk(c + 2, (c + 2) % NSTG);
            asm volatile("cp.async.commit_group;" ::: "memory");
        }

        const uint32_t stg = sbase + (c % NSTG) * STAGE_B;
        const uint32_t tAh = stg;
        const uint32_t tAl = stg + TILE_A;
        const uint32_t tBh = stg + 2 * TILE_A;
        const uint32_t tBl = tBh + TILE_BB;

#pragma unroll
        for (int ks = 0; ks < 2; ks++) {
            uint32_t a[2][4], bb[2][4];
            // term 1: Ah * Bh
#pragma unroll
            for (int mf = 0; mf < 2; mf++)
                ldsm4(a[mf], tAh, wm * 32 + mf * 16, ks);
#pragma unroll
            for (int p = 0; p < 2; p++)
                ldsm4(bb[p], tBh, wn * 32 + p * 16, ks);
#pragma unroll
            for (int mf = 0; mf < 2; mf++)
#pragma unroll
                for (int nf = 0; nf < 4; nf++) {
                    int p = nf >> 1, q = nf & 1;
                    mma16816(acc[mf][nf], a[mf], bb[p][q], bb[p][q + 2]);
                }
            // term 2: Al * Bh (reuse B frags)
#pragma unroll
            for (int mf = 0; mf < 2; mf++)
                ldsm4(a[mf], tAl, wm * 32 + mf * 16, ks);
#pragma unroll
            for (int mf = 0; mf < 2; mf++)
#pragma unroll
                for (int nf = 0; nf < 4; nf++) {
                    int p = nf >> 1, q = nf & 1;
                    mma16816(acc[mf][nf], a[mf], bb[p][q], bb[p][q + 2]);
                }
            // term 3 (3-term only): Ah * Bl
            if (!TWO) {
#pragma unroll
                for (int mf = 0; mf < 2; mf++)
                    ldsm4(a[mf], tAh, wm * 32 + mf * 16, ks);
#pragma unroll
                for (int p = 0; p < 2; p++)
                    ldsm4(bb[p], tBl, wn * 32 + p * 16, ks);
#pragma unroll
                for (int mf = 0; mf < 2; mf++)
#pragma unroll
                    for (int nf = 0; nf < 4; nf++) {
                        int p = nf >> 1, q = nf & 1;
                        mma16816(acc[mf][nf], a[mf], bb[p][q], bb[p][q + 2]);
                    }
            }
        }
    }

    const int r0 = m0 + wm * 32;
    const int c0 = n0l + wn * 32;
#pragma unroll
    for (int mf = 0; mf < 2; mf++) {
#pragma unroll
        for (int nf = 0; nf < 4; nf++) {
            int row = r0 + mf * 16 + (lane >> 2);
            int col = c0 + nf * 8 + (lane & 3) * 2;
            float bu0 = bias[col], bu1 = bias[col + 1];
            out[(size_t)row * HID + col]           = acc[mf][nf][0] + bu0;
            out[(size_t)row * HID + col + 1]       = acc[mf][nf][1] + bu1;
            out[(size_t)(row + 8) * HID + col]     = acc[mf][nf][2] + bu0;
            out[(size_t)(row + 8) * HID + col + 1] = acc[mf][nf][3] + bu1;
        }
    }
}

// ===================== QK GEMM (3-term, 512 CTAs) ===========================
__global__ void __launch_bounds__(256, 3)
qk_kernel(const __half* __restrict__ Ah, const __half* __restrict__ Al,
          const __half* __restrict__ Bh, const __half* __restrict__ Bl,
          const float* __restrict__ bq, const float* __restrict__ bk,
          float* __restrict__ oq, float* __restrict__ ok) {
    extern __shared__ char smem[];
    int sel = blockIdx.x >> 2;
    gemm_tile<false>(Ah, Al, Bh, Bl, sel ? bk : bq, sel ? ok : oq,
                     blockIdx.y * TM, blockIdx.x * TN, (blockIdx.x & 3) * TN,
                     smem);
}

// ===================== top-k body (uses caller smem) ========================
__device__ void topk_body(int bh, char* smembuf) {
    float* sval = (float*)smembuf;            // L floats
    float* wv = sval + L;                     // 8 floats
    int* wi = (int*)(wv + 8);                 // 8 ints
    int tid = threadIdx.x, lane = tid & 31, w = tid >> 5;

    for (int i = tid; i < L; i += 256) sval[i] = g_m[(size_t)bh * L + i];
    __syncthreads();

    for (int t = 0; t < N_TOP; t++) {
        float best = -INFINITY;
        int bi = 0x7fffffff;
        for (int i = tid; i < L; i += 256) {
            float v = sval[i];
            if (v > best) { best = v; bi = i; }
        }
#pragma unroll
        for (int o = 16; o; o >>= 1) {
            float ov = __shfl_xor_sync(0xffffffffu, best, o);
            int oi = __shfl_xor_sync(0xffffffffu, bi, o);
            if (ov > best || (ov == best && oi < bi)) { best = ov; bi = oi; }
        }
        if (lane == 0) { wv[w] = best; wi[w] = bi; }
        __syncthreads();
        if (tid < 8) {
            best = wv[tid];
            bi = wi[tid];
#pragma unroll
            for (int o = 4; o; o >>= 1) {
                float ov = __shfl_xor_sync(0xffu, best, o, 8);
                int oi = __shfl_xor_sync(0xffu, bi, o, 8);
                if (ov > best || (ov == best && oi < bi)) { best = ov; bi = oi; }
            }
            if (tid == 0) {
                g_mtop[bh * N_TOP + t] = bi;
                g_qmap[(size_t)bh * L + bi] = t;
                sval[bi] = -INFINITY;
            }
        }
        __syncthreads();
    }
}

// ===================== fused: V projection (256) + top-k (16) ===============
__global__ void __launch_bounds__(256, 3)
v_topk_kernel(const __half* __restrict__ Ah, const __half* __restrict__ Al,
              const __half* __restrict__ Bh, const __half* __restrict__ Bl,
              const float* __restrict__ bias, float* __restrict__ out) {
    extern __shared__ char smem[];
    int bid = blockIdx.x;
    if (bid < 256) {
        int nb = bid & 3, mb = bid >> 2;
        gemm_tile<true>(Ah, Al, Bh, Bl, bias, out,
                        mb * TM, nb * TN, nb * TN, smem);
    } else {
        topk_body(bid - 256, smem);
    }
}

// ===================== m-score (float4, 2 samples/warp) =====================
__global__ void mscore_kernel(const int* __restrict__ idx_sample) {
    int warp = (blockIdx.x * blockDim.x + threadIdx.x) >> 5;
    int lane = threadIdx.x & 31;
    if (warp >= B * NH * L) return;
    int l = warp % L;
    int h = (warp / L) % NH;
    int b = warp / (L * NH);

    int sub = lane & 15;
    int half = lane >> 4;

    const float4* qrow =
        (const float4*)(g_q + ((size_t)b * L + l) * HID + h * HD);
    float4 q4 = qrow[sub];

    float mx = -INFINITY, sm = 0.0f;
#pragma unroll 4
    for (int it = 0; it < SAMPLE_K / 2; it++) {
        int s = 2 * it + half;
        int ls = idx_sample[l * SAMPLE_K + s];
        const float4* kr =
            (const float4*)(g_k + ((size_t)b * L + ls) * HID + h * HD);
        float4 k4 = kr[sub];
        float d = q4.x * k4.x + q4.y * k4.y + q4.z * k4.z + q4.w * k4.w;
#pragma unroll
        for (int o = 8; o; o >>= 1) d += __shfl_xor_sync(0xffffffffu, d, o);
        mx = fmaxf(mx, d);
        sm += d;
    }
    float mx2 = __shfl_down_sync(0xffffffffu, mx, 16);
    float sm2 = __shfl_down_sync(0xffffffffu, sm, 16);
    if (lane == 0)
        g_m[warp] = fmaxf(mx, mx2) - (sm + sm2) * (1.0f / (float)L);
}

// ===================== attention body (8 queries / block) ===================
__device__ void attn_body(int blk, float* sc) {
    __shared__ float sq[QG][HD];
    __shared__ float inv[QG];
    __shared__ float red[4][QG][HD];

    const int tid = threadIdx.x;
    const int lane = tid & 31;
    const int w = tid >> 5;

    const int grp = blk % (N_TOP / QG);
    const int bh = blk / (N_TOP / QG);
    const int h = bh % NH;
    const int b = bh / NH;
    const int q0 = grp * QG;

#pragma unroll
    for (int r = 0; r < 2; r++) {
        int idx = tid + r * 256;
        int j = idx >> 6, d = idx & 63;
        int lq = g_mtop[bh * N_TOP + q0 + j];
        sq[j][d] = g_q[((size_t)b * L + lq) * HID + h * HD + d];
    }
    __syncthreads();

    {
        const int sub = lane & 15;
        const int half = lane >> 4;
        float4 q4[QG];
#pragma unroll
        for (int j = 0; j < QG; j++) q4[j] = *(const float4*)&sq[j][sub * 4];

        for (int base = w * 2; base < L; base += 16) {
            int key = base + half;
            const float4* kr =
                (const float4*)(g_k + ((size_t)b * L + key) * HID + h * HD);
            float4 k4 = kr[sub];
            float dj[QG];
#pragma unroll
            for (int j = 0; j < QG; j++) {
                float d = q4[j].x * k4.x + q4[j].y * k4.y +
                          q4[j].z * k4.z + q4[j].w * k4.w;
#pragma unroll
                for (int o = 8; o; o >>= 1)
                    d += __shfl_xor_sync(0xffffffffu, d, o);
                dj[j] = d * 0.125f;
            }
            if (sub == 0) {
#pragma unroll
                for (int j = 0; j < QG; j++) sc[j * L + key] = dj[j];
            }
        }
    }
    __syncthreads();

    {
        float mx = -INFINITY;
        for (int i = lane; i < L; i += 32) mx = fmaxf(mx, sc[w * L + i]);
#pragma unroll
        for (int o = 16; o; o >>= 1)
            mx = fmaxf(mx, __shfl_xor_sync(0xffffffffu, mx, o));
        float s = 0.0f;
        for (int i = lane; i < L; i += 32) {
            float e = __expf(sc[w * L + i] - mx);
            sc[w * L + i] = e;
            s += e;
        }
#pragma unroll
        for (int o = 16; o; o >>= 1) s += __shfl_xor_sync(0xffffffffu, s, o);
        if (lane == 0) inv[w] = 1.0f / s;
    }
    __syncthreads();

    {
        const int g = tid >> 6;
        const int d = tid & 63;
        float acc[QG];
#pragma unroll
        for (int j = 0; j < QG; j++) acc[j] = 0.0f;
        for (int key = g; key < L; key += 4) {
            float vv = g_v[((size_t)b * L + key) * HID + h * HD + d];
#pragma unroll
            for (int j = 0; j < QG; j++) acc[j] += sc[j * L + key] * vv;
        }
#pragma unroll
        for (int j = 0; j < QG; j++) red[g][j][d] = acc[j];
        __syncthreads();
        if (g == 0) {
#pragma unroll
            for (int j = 0; j < QG; j++) {
                float tot = red[0][j][d] + red[1][j][d] + red[2][j][d] +
                            red[3][j][d];
                g_ctxsel[((size_t)bh * N_TOP + q0 + j) * HD + d] =
                    tot * inv[j];
            }
        }
    }
}

__device__ void vmean_body(int bh) {
    __shared__ float sh[256];
    int b = bh / NH, h = bh % NH;
    int d = threadIdx.x % HD;
    int g = threadIdx.x / HD;
    float s = 0.0f;
    for (int l = g; l < L; l += 4)
        s += g_v[((size_t)b * L + l) * HID + h * HD + d];
    sh[threadIdx.x] = s;
    __syncthreads();
    if (g == 0)
        g_vmean[bh * HD + d] =
            (sh[d] + sh[d + 64] + sh[d + 128] + sh[d + 192]) * (1.0f / (float)L);
}

// ===================== fused: attn (80) + vmean (16) ========================
__global__ void __launch_bounds__(256)
attn_vmean_kernel() {
    extern __shared__ float sc[];
    if (blockIdx.x < B * NH * (N_TOP / QG))
        attn_body(blockIdx.x, sc);
    else
        vmean_body(blockIdx.x - B * NH * (N_TOP / QG));
}

// ===================== out-proj GEMM with inline ctx gather =================
__global__ void __launch_bounds__(256, 3)
outproj_kernel(const __half* __restrict__ Bh,
               const float* __restrict__ bias, float* __restrict__ out) {
    extern __shared__ char smem[];
    const uint32_t sbase = smem_u32(smem);

    const int tid = threadIdx.x;
    const int wid = tid >> 5;
    const int wm = wid >> 2;
    const int wn = wid & 3;
    const int lane = tid & 31;

    const int m0 = blockIdx.y * TM;
    const int n0 = blockIdx.x * TN;

    float acc[2][4][4];
#pragma unroll
    for (int i = 0; i < 2; i++)
#pragma unroll
        for (int j = 0; j < 4; j++)
#pragma unroll
            for (int t = 0; t < 4; t++) acc[i][j][t] = 0.0f;

    auto load_chunk = [&](int c, int stg) {
        const int k0 = c * KC;
        const uint32_t sb = sbase + stg * STAGE_B;
        {
            int row = tid >> 2;
            int seg = tid & 3;
            int gi = m0 + row;
            int b = gi >> 11;
            int l = gi & (L - 1);
            int h = k0 >> 6;
            int hd0 = (k0 & 63) + seg * 8;
            int bh = b * NH + h;
            int qi = g_qmap[(size_t)bh * L + l];
            const float* src = (qi >= 0)
                ? &g_ctxsel[((size_t)bh * N_TOP + qi) * HD + hd0]
                : &g_vmean[bh * HD + hd0];
            float4 v0 = ((const float4*)src)[0];
            float4 v1 = ((const float4*)src)[1];
            float f[8] = {v0.x, v0.y, v0.z, v0.w, v1.x, v1.y, v1.z, v1.w};
            __half hi[8], lo[8];
#pragma unroll
            for (int i = 0; i < 8; i++) {
                hi[i] = __float2half_rn(f[i]);
                lo[i] = __float2half_rn(f[i] - __half2float(hi[i]));
            }
            uint32_t off = swz((uint32_t)(row * 64 + seg * 16));
            *(uint4*)(smem + stg * STAGE_B + off) = *(const uint4*)hi;
            *(uint4*)(smem + stg * STAGE_B + TILE_A + off) = *(const uint4*)lo;
        }
        {
            const uint32_t tile = sb + 2 * TILE_A;
#pragma unroll
            for (int i = 0; i < 2; i++) {
                int idx = tid + i * 256;
                int row = idx >> 2;
                int c16 = idx & 3;
                const void* src =
                    Bh + (size_t)(n0 + row) * HID + k0 + c16 * 8;
                uint32_t dst = tile + swz((uint32_t)(row * 64 + c16 * 16));
                asm volatile("cp.async.cg.shared.global [%0], [%1], 16;"
                             :: "r"(dst), "l"(src));
            }
        }
    };

    load_chunk(0, 0);
    asm volatile("cp.async.commit_group;" ::: "memory");
    load_chunk(1, 1);
    asm volatile("cp.async.commit_group;" ::: "memory");

    for (int c = 0; c < NCH; c++) {
        if (c + 1 < NCH)
            asm volatile("cp.async.wait_group 1;" ::: "memory");
        else
            asm volatile("cp.async.wait_group 0;" ::: "memory");
        __syncthreads();
        if (c + 2 < NCH) {
            load_chunk(c + 2, (c + 2) % NSTG);
            asm volatile("cp.async.commit_group;" ::: "memory");
        }

        const uint32_t stg = sbase + (c % NSTG) * STAGE_B;
        const uint32_t tAh = stg;
        const uint32_t tAl = stg + TILE_A;
        const uint32_t tBh = stg + 2 * TILE_A;

#pragma unroll
        for (int ks = 0; ks < 2; ks++) {
            uint32_t a[2][4], bb[2][4];
#pragma unroll
            for (int mf = 0; mf < 2; mf++)
                ldsm4(a[mf], tAh, wm * 32 + mf * 16, ks);
#pragma unroll
            for (int p = 0; p < 2; p++)
                ldsm4(bb[p], tBh, wn * 32 + p * 16, ks);
#pragma unroll
            for (int mf = 0; mf < 2; mf++)
#pragma unroll
                for (int nf = 0; nf < 4; nf++) {
                    int p = nf >> 1, q = nf & 1;
                    mma16816(acc[mf][nf], a[mf], bb[p][q], bb[p][q + 2]);
                }
#pragma unroll
            for (int mf = 0; mf < 2; mf++)
                ldsm4(a[mf], tAl, wm * 32 + mf * 16, ks);
#pragma unroll
            for (int mf = 0; mf < 2; mf++)
#pragma unroll
                for (int nf = 0; nf < 4; nf++) {
                    int p = nf >> 1, q = nf & 1;
                    mma16816(acc[mf][nf], a[mf], bb[p][q], bb[p][q + 2]);
                }
        }
    }

    const int r0 = m0 + wm * 32;
    const int c0 = n0 + wn * 32;
#pragma unroll
    for (int mf = 0; mf < 2; mf++) {
#pragma unroll
        for (int nf = 0; nf < 4; nf++) {
            int row = r0 + mf * 16 + (lane >> 2);
            int col = c0 + nf * 8 + (lane & 3) * 2;
            float bu0 = bias[col], bu1 = bias[col + 1];
            out[(size_t)row * HID + col]           = acc[mf][nf][0] + bu0;
            out[(size_t)row * HID + col + 1]       = acc[mf][nf][1] + bu1;
            out[(size_t)(row + 8) * HID + col]     = acc[mf][nf][2] + bu0;
            out[(size_t)(row + 8) * HID + col + 1] = acc[mf][nf][3] + bu1;
        }
    }
}

// ===================== launch ===============================================
extern "C" void kernel_launch(void* const* d_in, const int* in_sizes, int n_in,
                              void* d_out, int out_size) {
    const float* hidden = (const float*)d_in[0];
    const int* idxs = (const int*)d_in[1];
    const float* Wq = (const float*)d_in[2];
    const float* bq = (const float*)d_in[3];
    const float* Wk = (const float*)d_in[4];
    const float* bk = (const float*)d_in[5];
    const float* Wv = (const float*)d_in[6];
    const float* bv = (const float*)d_in[7];
    const float* Wo = (const float*)d_in[8];
    const float* bo = (const float*)d_in[9];
    float* out = (float*)d_out;

    float *pq, *pk, *pv;
    cudaGetSymbolAddress((void**)&pq, g_q);
    cudaGetSymbolAddress((void**)&pk, g_k);
    cudaGetSymbolAddress((void**)&pv, g_v);
    __half *pah, *pal, *pwh, *pwl;
    cudaGetSymbolAddress((void**)&pah, g_ah);
    cudaGetSymbolAddress((void**)&pal, g_al);
    cudaGetSymbolAddress((void**)&pwh, g_wh);
    cudaGetSymbolAddress((void**)&pwl, g_wl);

    cudaFuncSetAttribute(qk_kernel,
                         cudaFuncAttributeMaxDynamicSharedMemorySize, GEMM_SMEM);
    cudaFuncSetAttribute(v_topk_kernel,
                         cudaFuncAttributeMaxDynamicSharedMemorySize, GEMM_SMEM);
    cudaFuncSetAttribute(outproj_kernel,
                         cudaFuncAttributeMaxDynamicSharedMemorySize, GEMM_SMEM);
    cudaFuncSetAttribute(attn_vmean_kernel,
                         cudaFuncAttributeMaxDynamicSharedMemorySize,
                         QG * L * (int)sizeof(float));

    const int NW = HID * HID;

    // 1: all splits + qmap init
    split_all<<<3200, 256>>>(hidden, Wq, Wk, Wv, Wo);
    // 2: Q,K projection (3-term), 8 x 64 = 512 CTAs
    dim3 qk_grid(8, (B * L) / TM);
    qk_kernel<<<qk_grid, 256, GEMM_SMEM>>>(pah, pal, pwh, pwl, bq, bk, pq, pk);
    // 3: m-score
    mscore_kernel<<<(B * NH * L) / 8, 256>>>(idxs);
    // 4 (profiled): V projection (256) + top-k (16)
    v_topk_kernel<<<272, 256, GEMM_SMEM>>>(
        pah, pal, pwh + 2 * (size_t)NW, pwl + 2 * (size_t)NW, bv, pv);
    // 5: attention (80) + v-mean (16)
    attn_vmean_kernel<<<96, 256, QG * L * sizeof(float)>>>();
    // 6: output projection with inline ctx gather (2-term)
    dim3 o_grid(4, (B * L) / TM);
    outproj_kernel<<<o_grid, 256, GEMM_SMEM>>>(pwh + 3 * (size_t)NW, bo, out);
}

// round 17
// speedup vs baseline: 1.3047x; 1.1850x over previous
#include <cuda_runtime.h>
#include <cuda_fp16.h>
#include <math.h>
#include <stdint.h>

#define B 2
#define L 2048
#define HID 512
#define NH 8
#define HD 64
#define SAMPLE_K 40
#define N_TOP 40
#define QG 8   // queries per attention block

// ===================== helpers ==============================================
__device__ __forceinline__ uint32_t smem_u32(const void* p) {
    uint32_t a;
    asm("{ .reg .u64 t; cvta.to.shared.u64 t, %1; cvt.u32.u64 %0, t; }"
        : "=r"(a) : "l"(p));
    return a;
}

// ===================== scratch ==============================================
__device__ float g_q[B * L * HID];
__device__ float g_k[B * L * HID];
__device__ float g_v[B * L * HID];
__device__ float g_m[B * NH * L];
__device__ int   g_mtop[B * NH * N_TOP];
__device__ int   g_qmap[B * NH * L];
__device__ float g_vmean[B * NH * HD];
__device__ float g_ctxsel[B * NH * N_TOP * HD];
// fp16 hi/lo splits
__device__ __half g_ah[B * L * HID];
__device__ __half g_al[B * L * HID];
__device__ __half g_wh[4 * HID * HID];   // Wq,Wk,Wv,Wo
__device__ __half g_wl[4 * HID * HID];

// ===================== fp32 -> fp16 hi/lo split (float4) ====================
__device__ __forceinline__ void split4_store(float4 v, __half* hi,
                                             __half* lo, size_t i4) {
    __half h0 = __float2half_rn(v.x);
    __half h1 = __float2half_rn(v.y);
    __half h2 = __float2half_rn(v.z);
    __half h3 = __float2half_rn(v.w);
    __half2* hp = (__half2*)(hi + i4 * 4);
    __half2* lp = (__half2*)(lo + i4 * 4);
    hp[0] = __half2(h0, h1);
    hp[1] = __half2(h2, h3);
    lp[0] = __half2(__float2half_rn(v.x - __half2float(h0)),
                    __float2half_rn(v.y - __half2float(h1)));
    lp[1] = __half2(__float2half_rn(v.z - __half2float(h2)),
                    __float2half_rn(v.w - __half2float(h3)));
}

// ===================== fused init: splits + weights + qmap ==================
__global__ void split_all(const float* __restrict__ hidden,
                          const float* __restrict__ w0,
                          const float* __restrict__ w1,
                          const float* __restrict__ w2,
                          const float* __restrict__ w3) {
    const int NW4 = HID * HID / 4;   // 65536
    int bid = blockIdx.x;
    int tid = threadIdx.x;
    if (bid < 2048) {
        int i4 = bid * 256 + tid;
        split4_store(((const float4*)hidden)[i4], g_ah, g_al, i4);
    } else if (bid < 3072) {
        int wb = bid - 2048;
        int sel = wb >> 8;
        int i = (wb & 255) * 256 + tid;
        const float* w = sel == 0 ? w0 : (sel == 1 ? w1 : (sel == 2 ? w2 : w3));
        split4_store(((const float4*)w)[i], g_wh, g_wl,
                     (size_t)sel * NW4 + i);
    } else {
        int i = (bid - 3072) * 256 + tid;
        if (i < B * NH * L) g_qmap[i] = -1;
    }
}

// ===================== HMMA split-fp16 GEMM tile (TM=64) ====================
#define TM 64
#define TN 128
#define KC 32
#define NCH (HID / KC)                 // 16
#define TILE_A (TM * KC * 2)           // 4096
#define TILE_BB (TN * KC * 2)          // 8192
#define STAGE_B (2 * TILE_A + 2 * TILE_BB)  // 24576
#define NSTG 3
#define GEMM_SMEM (NSTG * STAGE_B)     // 73728

__device__ __forceinline__ uint32_t swz(uint32_t off) {
    return off ^ ((off >> 3) & 0x30);
}

__device__ __forceinline__ void ldsm4(uint32_t r[4], uint32_t tile,
                                      int rowbase, int ks) {
    int lane = threadIdx.x & 31;
    int row = rowbase + (lane & 15);
    int c16 = ks * 2 + (lane >> 4);
    uint32_t addr = tile + swz((uint32_t)(row * 64 + c16 * 16));
    asm volatile("ldmatrix.sync.aligned.m8n8.x4.shared.b16 {%0,%1,%2,%3}, [%4];"
                 : "=r"(r[0]), "=r"(r[1]), "=r"(r[2]), "=r"(r[3]) : "r"(addr));
}

__device__ __forceinline__ void mma16816(float c[4], const uint32_t a[4],
                                         uint32_t b0, uint32_t b1) {
    asm volatile(
        "mma.sync.aligned.m16n8k16.row.col.f32.f16.f16.f32 "
        "{%0,%1,%2,%3},{%4,%5,%6,%7},{%8,%9},{%0,%1,%2,%3};"
        : "+f"(c[0]), "+f"(c[1]), "+f"(c[2]), "+f"(c[3])
        : "r"(a[0]), "r"(a[1]), "r"(a[2]), "r"(a[3]), "r"(b0), "r"(b1));
}

// generic gemm tile: A from splits, B from weight splits.
template <bool TWO>
__device__ __forceinline__ void gemm_tile(
    const __half* __restrict__ Ah, const __half* __restrict__ Al,
    const __half* __restrict__ Bh, const __half* __restrict__ Bl,
    const float* __restrict__ bias, float* __restrict__ out,
    int m0, int n0g, int n0l, char* smem) {
    const uint32_t sbase = smem_u32(smem);

    const int tid = threadIdx.x;
    const int wid = tid >> 5;
    const int wm = wid >> 2;
    const int wn = wid & 3;
    const int lane = tid & 31;

    float acc[2][4][4];
#pragma unroll
    for (int i = 0; i < 2; i++)
#pragma unroll
        for (int j = 0; j < 4; j++)
#pragma unroll
            for (int t = 0; t < 4; t++) acc[i][j][t] = 0.0f;

    auto load_chunk = [&](int c, int stg) {
        const int k0 = c * KC;
        const uint32_t sb = sbase + stg * STAGE_B;
#pragma unroll
        for (int t = 0; t < 2; t++) {
            const __half* src0 = t ? Al : Ah;
            const uint32_t tile = sb + t * TILE_A;
            int row = tid >> 2;
            int c16 = tid & 3;
            const void* src = src0 + (size_t)(m0 + row) * HID + k0 + c16 * 8;
            uint32_t dst = tile + swz((uint32_t)(row * 64 + c16 * 16));
            asm volatile("cp.async.cg.shared.global [%0], [%1], 16;"
                         :: "r"(dst), "l"(src));
        }
#pragma unroll
        for (int t = 0; t < (TWO ? 1 : 2); t++) {
            const __half* src0 = t ? Bl : Bh;
            const uint32_t tile = sb + 2 * TILE_A + t * TILE_BB;
#pragma unroll
            for (int i = 0; i < 2; i++) {
                int idx = tid + i * 256;
                int row = idx >> 2;
                int c16 = idx & 3;
                const void* src =
                    src0 + (size_t)(n0g + row) * HID + k0 + c16 * 8;
                uint32_t dst = tile + swz((uint32_t)(row * 64 + c16 * 16));
                asm volatile("cp.async.cg.shared.global [%0], [%1], 16;"
                             :: "r"(dst), "l"(src));
            }
        }
    };

    load_chunk(0, 0);
    asm volatile("cp.async.commit_group;" ::: "memory");
    load_chunk(1, 1);
    asm volatile("cp.async.commit_group;" ::: "memory");

    for (int c = 0; c < NCH; c++) {
        if (c + 1 < NCH)
            asm volatile("cp.async.wait_group 1;" ::: "memory");
        else
            asm volatile("cp.async.wait_group 0;" ::: "memory");
        __syncthreads();
        if (c + 2 < NCH) {
            load_chunk(c + 2, (c + 2) % NSTG);
            asm volatile("cp.async.commit_group;" ::: "memory");
        }

        const uint32_t stg = sbase + (c % NSTG) * STAGE_B;
        const uint32_t tAh = stg;
        const uint32_t tAl = stg + TILE_A;
        const uint32_t tBh = stg + 2 * TILE_A;
        const uint32_t tBl = tBh + TILE_BB;

#pragma unroll
        for (int ks = 0; ks < 2; ks++) {
            uint32_t a[2][4], bb[2][4];
            // term 1: Ah * Bh
#pragma unroll
            for (int mf = 0; mf < 2; mf++)
                ldsm4(a[mf], tAh, wm * 32 + mf * 16, ks);
#pragma unroll
            for (int p = 0; p < 2; p++)
                ldsm4(bb[p], tBh, wn * 32 + p * 16, ks);
#pragma unroll
            for (int mf = 0; mf < 2; mf++)
#pragma unroll
                for (int nf = 0; nf < 4; nf++) {
                    int p = nf >> 1, q = nf & 1;
                    mma16816(acc[mf][nf], a[mf], bb[p][q], bb[p][q + 2]);
                }
            // term 2: Al * Bh (reuse B frags)
#pragma unroll
            for (int mf = 0; mf < 2; mf++)
                ldsm4(a[mf], tAl, wm * 32 + mf * 16, ks);
#pragma unroll
            for (int mf = 0; mf < 2; mf++)
#pragma unroll
                for (int nf = 0; nf < 4; nf++) {
                    int p = nf >> 1, q = nf & 1;
                    mma16816(acc[mf][nf], a[mf], bb[p][q], bb[p][q + 2]);
                }
            // term 3 (3-term only): Ah * Bl
            if (!TWO) {
#pragma unroll
                for (int mf = 0; mf < 2; mf++)
                    ldsm4(a[mf], tAh, wm * 32 + mf * 16, ks);
#pragma unroll
                for (int p = 0; p < 2; p++)
                    ldsm4(bb[p], tBl, wn * 32 + p * 16, ks);
#pragma unroll
                for (int mf = 0; mf < 2; mf++)
#pragma unroll
                    for (int nf = 0; nf < 4; nf++) {
                        int p = nf >> 1, q = nf & 1;
                        mma16816(acc[mf][nf], a[mf], bb[p][q], bb[p][q + 2]);
                    }
            }
        }
    }

    const int r0 = m0 + wm * 32;
    const int c0 = n0l + wn * 32;
#pragma unroll
    for (int mf = 0; mf < 2; mf++) {
#pragma unroll
        for (int nf = 0; nf < 4; nf++) {
            int row = r0 + mf * 16 + (lane >> 2);
            int col = c0 + nf * 8 + (lane & 3) * 2;
            float bu0 = bias[col], bu1 = bias[col + 1];
            out[(size_t)row * HID + col]           = acc[mf][nf][0] + bu0;
            out[(size_t)row * HID + col + 1]       = acc[mf][nf][1] + bu1;
            out[(size_t)(row + 8) * HID + col]     = acc[mf][nf][2] + bu0;
            out[(size_t)(row + 8) * HID + col + 1] = acc[mf][nf][3] + bu1;
        }
    }
}

// ===================== QK GEMM (3-term, 512 CTAs) ===========================
__global__ void __launch_bounds__(256, 3)
qk_kernel(const __half* __restrict__ Ah, const __half* __restrict__ Al,
          const __half* __restrict__ Bh, const __half* __restrict__ Bl,
          const float* __restrict__ bq, const float* __restrict__ bk,
          float* __restrict__ oq, float* __restrict__ ok) {
    extern __shared__ char smem[];
    int sel = blockIdx.x >> 2;
    gemm_tile<false>(Ah, Al, Bh, Bl, sel ? bk : bq, sel ? ok : oq,
                     blockIdx.y * TM, blockIdx.x * TN, (blockIdx.x & 3) * TN,
                     smem);
}

// ===================== top-k body (uses caller smem) ========================
__device__ void topk_body(int bh, char* smembuf) {
    float* sval = (float*)smembuf;            // L floats
    float* wv = sval + L;                     // 8 floats
    int* wi = (int*)(wv + 8);                 // 8 ints
    int tid = threadIdx.x, lane = tid & 31, w = tid >> 5;

    for (int i = tid; i < L; i += 256) sval[i] = g_m[(size_t)bh * L + i];
    __syncthreads();

    for (int t = 0; t < N_TOP; t++) {
        float best = -INFINITY;
        int bi = 0x7fffffff;
        for (int i = tid; i < L; i += 256) {
            float v = sval[i];
            if (v > best) { best = v; bi = i; }
        }
#pragma unroll
        for (int o = 16; o; o >>= 1) {
            float ov = __shfl_xor_sync(0xffffffffu, best, o);
            int oi = __shfl_xor_sync(0xffffffffu, bi, o);
            if (ov > best || (ov == best && oi < bi)) { best = ov; bi = oi; }
        }
        if (lane == 0) { wv[w] = best; wi[w] = bi; }
        __syncthreads();
        if (tid < 8) {
            best = wv[tid];
            bi = wi[tid];
#pragma unroll
            for (int o = 4; o; o >>= 1) {
                float ov = __shfl_xor_sync(0xffu, best, o, 8);
                int oi = __shfl_xor_sync(0xffu, bi, o, 8);
                if (ov > best || (ov == best && oi < bi)) { best = ov; bi = oi; }
            }
            if (tid == 0) {
                g_mtop[bh * N_TOP + t] = bi;
                g_qmap[(size_t)bh * L + bi] = t;
                sval[bi] = -INFINITY;
            }
        }
        __syncthreads();
    }
}

// ===================== fused: V projection (256) + top-k (16) ===============
__global__ void __launch_bounds__(256, 3)
v_topk_kernel(const __half* __restrict__ Ah, const __half* __restrict__ Al,
              const __half* __restrict__ Bh, const __half* __restrict__ Bl,
              const float* __restrict__ bias, float* __restrict__ out) {
    extern __shared__ char smem[];
    int bid = blockIdx.x;
    if (bid < 256) {
        int nb = bid & 3, mb = bid >> 2;
        gemm_tile<true>(Ah, Al, Bh, Bl, bias, out,
                        mb * TM, nb * TN, nb * TN, smem);
    } else {
        topk_body(bid - 256, smem);
    }
}

// ===================== m-score (float4, 2 samples/warp) =====================
__global__ void mscore_kernel(const int* __restrict__ idx_sample) {
    int warp = (blockIdx.x * blockDim.x + threadIdx.x) >> 5;
    int lane = threadIdx.x & 31;
    if (warp >= B * NH * L) return;
    int l = warp % L;
    int h = (warp / L) % NH;
    int b = warp / (L * NH);

    int sub = lane & 15;
    int half = lane >> 4;

    const float4* qrow =
        (const float4*)(g_q + ((size_t)b * L + l) * HID + h * HD);
    float4 q4 = qrow[sub];

    float mx = -INFINITY, sm = 0.0f;
#pragma unroll 4
    for (int it = 0; it < SAMPLE_K / 2; it++) {
        int s = 2 * it + half;
        int ls = idx_sample[l * SAMPLE_K + s];
        const float4* kr =
            (const float4*)(g_k + ((size_t)b * L + ls) * HID + h * HD);
        float4 k4 = kr[sub];
        float d = q4.x * k4.x + q4.y * k4.y + q4.z * k4.z + q4.w * k4.w;
#pragma unroll
        for (int o = 8; o; o >>= 1) d += __shfl_xor_sync(0xffffffffu, d, o);
        mx = fmaxf(mx, d);
        sm += d;
    }
    float mx2 = __shfl_down_sync(0xffffffffu, mx, 16);
    float sm2 = __shfl_down_sync(0xffffffffu, sm, 16);
    if (lane == 0)
        g_m[warp] = fmaxf(mx, mx2) - (sm + sm2) * (1.0f / (float)L);
}

// ===================== attention body (8 queries, 512 threads) ==============
__device__ void attn_body(int blk, float* sc) {
    __shared__ float sq[QG][HD];
    __shared__ float inv[QG];
    __shared__ float red[8][QG][HD];

    const int tid = threadIdx.x;       // 0..511
    const int lane = tid & 31;
    const int w = tid >> 5;            // 0..15

    const int grp = blk % (N_TOP / QG);
    const int bh = blk / (N_TOP / QG);
    const int h = bh % NH;
    const int b = bh / NH;
    const int q0 = grp * QG;

    // load 8 query rows (512 threads = exactly QG*HD)
    {
        int j = tid >> 6, d = tid & 63;
        int lq = g_mtop[bh * N_TOP + q0 + j];
        sq[j][d] = g_q[((size_t)b * L + lq) * HID + h * HD + d];
    }
    __syncthreads();

    // ---- scores: half-warp per key, 16 warps cover 32 keys/iter ----
    {
        const int sub = lane & 15;
        const int half = lane >> 4;
        float4 q4[QG];
#pragma unroll
        for (int j = 0; j < QG; j++) q4[j] = *(const float4*)&sq[j][sub * 4];

        for (int base = w * 2; base < L; base += 32) {
            int key = base + half;
            const float4* kr =
                (const float4*)(g_k + ((size_t)b * L + key) * HID + h * HD);
            float4 k4 = kr[sub];
            float dj[QG];
#pragma unroll
            for (int j = 0; j < QG; j++) {
                float d = q4[j].x * k4.x + q4[j].y * k4.y +
                          q4[j].z * k4.z + q4[j].w * k4.w;
#pragma unroll
                for (int o = 8; o; o >>= 1)
                    d += __shfl_xor_sync(0xffffffffu, d, o);
                dj[j] = d * 0.125f;
            }
            if (sub == 0) {
#pragma unroll
                for (int j = 0; j < QG; j++) sc[j * L + key] = dj[j];
            }
        }
    }
    __syncthreads();

    // ---- softmax: warps 0..7, warp w handles query row w ----
    if (w < QG) {
        float mx = -INFINITY;
        for (int i = lane; i < L; i += 32) mx = fmaxf(mx, sc[w * L + i]);
#pragma unroll
        for (int o = 16; o; o >>= 1)
            mx = fmaxf(mx, __shfl_xor_sync(0xffffffffu, mx, o));
        float s = 0.0f;
        for (int i = lane; i < L; i += 32) {
            float e = __expf(sc[w * L + i] - mx);
            sc[w * L + i] = e;
            s += e;
        }
#pragma unroll
        for (int o = 16; o; o >>= 1) s += __shfl_xor_sync(0xffffffffu, s, o);
        if (lane == 0) inv[w] = 1.0f / s;
    }
    __syncthreads();

    // ---- ctx: 8 key-groups x 64 d-threads ----
    {
        const int g = tid >> 6;        // 0..7
        const int d = tid & 63;
        float acc[QG];
#pragma unroll
        for (int j = 0; j < QG; j++) acc[j] = 0.0f;
        for (int key = g; key < L; key += 8) {
            float vv = g_v[((size_t)b * L + key) * HID + h * HD + d];
#pragma unroll
            for (int j = 0; j < QG; j++) acc[j] += sc[j * L + key] * vv;
        }
#pragma unroll
        for (int j = 0; j < QG; j++) red[g][j][d] = acc[j];
        __syncthreads();
        if (g == 0) {
#pragma unroll
            for (int j = 0; j < QG; j++) {
                float tot = red[0][j][d] + red[1][j][d] + red[2][j][d] +
                            red[3][j][d] + red[4][j][d] + red[5][j][d] +
                            red[6][j][d] + red[7][j][d];
                g_ctxsel[((size_t)bh * N_TOP + q0 + j) * HD + d] =
                    tot * inv[j];
            }
        }
    }
}

__device__ void vmean_body(int bh) {
    __shared__ float sh[512];
    int b = bh / NH, h = bh % NH;
    int d = threadIdx.x & 63;
    int g = threadIdx.x >> 6;          // 0..7
    float s = 0.0f;
    for (int l = g; l < L; l += 8)
        s += g_v[((size_t)b * L + l) * HID + h * HD + d];
    sh[threadIdx.x] = s;
    __syncthreads();
    if (g == 0) {
        float tot = sh[d] + sh[d + 64] + sh[d + 128] + sh[d + 192] +
                    sh[d + 256] + sh[d + 320] + sh[d + 384] + sh[d + 448];
        g_vmean[bh * HD + d] = tot * (1.0f / (float)L);
    }
}

// ===================== fused: attn (80) + vmean (16), 512 threads ===========
__global__ void __launch_bounds__(512)
attn_vmean_kernel() {
    extern __shared__ float sc[];
    if (blockIdx.x < B * NH * (N_TOP / QG))
        attn_body(blockIdx.x, sc);
    else
        vmean_body(blockIdx.x - B * NH * (N_TOP / QG));
}

// ===================== out-proj GEMM with inline ctx gather =================
__global__ void __launch_bounds__(256, 3)
outproj_kernel(const __half* __restrict__ Bh,
               const float* __restrict__ bias, float* __restrict__ out) {
    extern __shared__ char smem[];
    const uint32_t sbase = smem_u32(smem);

    const int tid = threadIdx.x;
    const int wid = tid >> 5;
    const int wm = wid >> 2;
    const int wn = wid & 3;
    const int lane = tid & 31;

    const int m0 = blockIdx.y * TM;
    const int n0 = blockIdx.x * TN;

    float acc[2][4][4];
#pragma unroll
    for (int i = 0; i < 2; i++)
#pragma unroll
        for (int j = 0; j < 4; j++)
#pragma unroll
            for (int t = 0; t < 4; t++) acc[i][j][t] = 0.0f;

    auto load_chunk = [&](int c, int stg) {
        const int k0 = c * KC;
        const uint32_t sb = sbase + stg * STAGE_B;
        {
            int row = tid >> 2;
            int seg = tid & 3;
            int gi = m0 + row;
            int b = gi >> 11;
            int l = gi & (L - 1);
            int h = k0 >> 6;
            int hd0 = (k0 & 63) + seg * 8;
            int bh = b * NH + h;
            int qi = g_qmap[(size_t)bh * L + l];
            const float* src = (qi >= 0)
                ? &g_ctxsel[((size_t)bh * N_TOP + qi) * HD + hd0]
                : &g_vmean[bh * HD + hd0];
            float4 v0 = ((const float4*)src)[0];
            float4 v1 = ((const float4*)src)[1];
            float f[8] = {v0.x, v0.y, v0.z, v0.w, v1.x, v1.y, v1.z, v1.w};
            __half hi[8], lo[8];
#pragma unroll
            for (int i = 0; i < 8; i++) {
                hi[i] = __float2half_rn(f[i]);
                lo[i] = __float2half_rn(f[i] - __half2float(hi[i]));
            }
            uint32_t off = swz((uint32_t)(row * 64 + seg * 16));
            *(uint4*)(smem + stg * STAGE_B + off) = *(const uint4*)hi;
            *(uint4*)(smem + stg * STAGE_B + TILE_A + off) = *(const uint4*)lo;
        }
        {
            const uint32_t tile = sb + 2 * TILE_A;
#pragma unroll
            for (int i = 0; i < 2; i++) {
                int idx = tid + i * 256;
                int row = idx >> 2;
                int c16 = idx & 3;
                const void* src =
                    Bh + (size_t)(n0 + row) * HID + k0 + c16 * 8;
                uint32_t dst = tile + swz((uint32_t)(row * 64 + c16 * 16));
                asm volatile("cp.async.cg.shared.global [%0], [%1], 16;"
                             :: "r"(dst), "l"(src));
            }
        }
    };

    load_chunk(0, 0);
    asm volatile("cp.async.commit_group;" ::: "memory");
    load_chunk(1, 1);
    asm volatile("cp.async.commit_group;" ::: "memory");

    for (int c = 0; c < NCH; c++) {
        if (c + 1 < NCH)
            asm volatile("cp.async.wait_group 1;" ::: "memory");
        else
            asm volatile("cp.async.wait_group 0;" ::: "memory");
        __syncthreads();
        if (c + 2 < NCH) {
            load_chunk(c + 2, (c + 2) % NSTG);
            asm volatile("cp.async.commit_group;" ::: "memory");
        }

        const uint32_t stg = sbase + (c % NSTG) * STAGE_B;
        const uint32_t tAh = stg;
        const uint32_t tAl = stg + TILE_A;
        const uint32_t tBh = stg + 2 * TILE_A;

#pragma unroll
        for (int ks = 0; ks < 2; ks++) {
            uint32_t a[2][4], bb[2][4];
#pragma unroll
            for (int mf = 0; mf < 2; mf++)
                ldsm4(a[mf], tAh, wm * 32 + mf * 16, ks);
#pragma unroll
            for (int p = 0; p < 2; p++)
                ldsm4(bb[p], tBh, wn * 32 + p * 16, ks);
#pragma unroll
            for (int mf = 0; mf < 2; mf++)
#pragma unroll
                for (int nf = 0; nf < 4; nf++) {
                    int p = nf >> 1, q = nf & 1;
                    mma16816(acc[mf][nf], a[mf], bb[p][q], bb[p][q + 2]);
                }
#pragma unroll
            for (int mf = 0; mf < 2; mf++)
                ldsm4(a[mf], tAl, wm * 32 + mf * 16, ks);
#pragma unroll
            for (int mf = 0; mf < 2; mf++)
#pragma unroll
                for (int nf = 0; nf < 4; nf++) {
                    int p = nf >> 1, q = nf & 1;
                    mma16816(acc[mf][nf], a[mf], bb[p][q], bb[p][q + 2]);
                }
        }
    }

    const int r0 = m0 + wm * 32;
    const int c0 = n0 + wn * 32;
#pragma unroll
    for (int mf = 0; mf < 2; mf++) {
#pragma unroll
        for (int nf = 0; nf < 4; nf++) {
            int row = r0 + mf * 16 + (lane >> 2);
            int col = c0 + nf * 8 + (lane & 3) * 2;
            float bu0 = bias[col], bu1 = bias[col + 1];
            out[(size_t)row * HID + col]           = acc[mf][nf][0] + bu0;
            out[(size_t)row * HID + col + 1]       = acc[mf][nf][1] + bu1;
            out[(size_t)(row + 8) * HID + col]     = acc[mf][nf][2] + bu0;
            out[(size_t)(row + 8) * HID + col + 1] = acc[mf][nf][3] + bu1;
        }
    }
}

// ===================== launch ===============================================
extern "C" void kernel_launch(void* const* d_in, const int* in_sizes, int n_in,
                              void* d_out, int out_size) {
    const float* hidden = (const float*)d_in[0];
    const int* idxs = (const int*)d_in[1];
    const float* Wq = (const float*)d_in[2];
    const float* bq = (const float*)d_in[3];
    const float* Wk = (const float*)d_in[4];
    const float* bk = (const float*)d_in[5];
    const float* Wv = (const float*)d_in[6];
    const float* bv = (const float*)d_in[7];
    const float* Wo = (const float*)d_in[8];
    const float* bo = (const float*)d_in[9];
    float* out = (float*)d_out;

    float *pq, *pk, *pv;
    cudaGetSymbolAddress((void**)&pq, g_q);
    cudaGetSymbolAddress((void**)&pk, g_k);
    cudaGetSymbolAddress((void**)&pv, g_v);
    __half *pah, *pal, *pwh, *pwl;
    cudaGetSymbolAddress((void**)&pah, g_ah);
    cudaGetSymbolAddress((void**)&pal, g_al);
    cudaGetSymbolAddress((void**)&pwh, g_wh);
    cudaGetSymbolAddress((void**)&pwl, g_wl);

    cudaFuncSetAttribute(qk_kernel,
                         cudaFuncAttributeMaxDynamicSharedMemorySize, GEMM_SMEM);
    cudaFuncSetAttribute(v_topk_kernel,
                         cudaFuncAttributeMaxDynamicSharedMemorySize, GEMM_SMEM);
    cudaFuncSetAttribute(outproj_kernel,
                         cudaFuncAttributeMaxDynamicSharedMemorySize, GEMM_SMEM);
    cudaFuncSetAttribute(attn_vmean_kernel,
                         cudaFuncAttributeMaxDynamicSharedMemorySize,
                         QG * L * (int)sizeof(float));

    const int NW = HID * HID;

    // 1: all splits + qmap init
    split_all<<<3200, 256>>>(hidden, Wq, Wk, Wv, Wo);
    // 2: Q,K projection (3-term), 8 x 64 = 512 CTAs
    dim3 qk_grid(8, (B * L) / TM);
    qk_kernel<<<qk_grid, 256, GEMM_SMEM>>>(pah, pal, pwh, pwl, bq, bk, pq, pk);
    // 3: m-score
    mscore_kernel<<<(B * NH * L) / 8, 256>>>(idxs);
    // 4 (profiled): V projection (256) + top-k (16)
    v_topk_kernel<<<272, 256, GEMM_SMEM>>>(
        pah, pal, pwh + 2 * (size_t)NW, pwl + 2 * (size_t)NW, bv, pv);
    // 5: attention (80) + v-mean (16), 512 threads/block
    attn_vmean_kernel<<<96, 512, QG * L * sizeof(float)>>>();
    // 6: output projection with inline ctx gather (2-term)
    dim3 o_grid(4, (B * L) / TM);
    outproj_kernel<<<o_grid, 256, GEMM_SMEM>>>(pwh + 3 * (size_t)NW, bo, out);
}